// round 8
// baseline (speedup 1.0000x reference)
#include <cuda_runtime.h>
#include <cfloat>

// Caffe-style RoI max pooling, bit-exact to the XLA-executed JAX reference.
//   x: [2,256,64,64] f32, rois: [2048,5] f32 -> out: [2048,256,7,7] f32
// Numerics: bin = roi_dim * RN(1/7) (0x3E124925) — XLA rewrites const-division
// into reciprocal multiply; rintf == jnp.round; __fmul_rn for boundary muls.
//
// K1: transpose x -> xt[b][h][w][c] (channels-last) device scratch.
// K2: one block per roi, one bin per warp, warp-uniform bounds, two LDG.128
//     per cell (all 256 channels). Bins processed in two groups (28 + 21)
//     through a 29 KB sbin so 6 blocks/SM fit; __launch_bounds__(256,6)
//     caps regs at 42 -> 48 warps/SM (75% occ) vs 32 before.

#define PH 7
#define PW 7
#define SCALE 0.0625f
#define NTHR 256
#define SPITCH 260                 // floats per bin row (16B-aligned rows)
#define SROWS 28                   // sbin rows (max group size)

__device__ float g_xt[2 * 64 * 64 * 256];   // [b][h][w][c]

// ---- K1: [b][c][hw] -> [b][hw][c] tiled transpose ----
__global__ void __launch_bounds__(256)
transpose_kernel(const float* __restrict__ x)
{
    __shared__ float t[32][33];
    const int tx = threadIdx.x & 31;
    const int ty = threadIdx.x >> 5;
    const int hw0 = blockIdx.x * 32;
    const int c0  = blockIdx.y * 32;
    const int b   = blockIdx.z;
    const float* src = x + (size_t)b * 256 * 4096;
    float* dst = g_xt + (size_t)b * 4096 * 256;

    #pragma unroll
    for (int i = 0; i < 32; i += 8)
        t[ty + i][tx] = src[(size_t)(c0 + ty + i) * 4096 + hw0 + tx];
    __syncthreads();
    #pragma unroll
    for (int i = 0; i < 32; i += 8)
        dst[(size_t)(hw0 + ty + i) * 256 + c0 + tx] = t[tx][ty + i];
}

__device__ __forceinline__ float4 fmax4(float4 a, float4 b) {
    return make_float4(fmaxf(a.x, b.x), fmaxf(a.y, b.y),
                       fmaxf(a.z, b.z), fmaxf(a.w, b.w));
}

// ---- K2: pooling ----
__global__ void __launch_bounds__(NTHR, 6)
roipool_cl_kernel(const float* __restrict__ rois,
                  float* __restrict__ out)
{
    __shared__ float sbin[SROWS * SPITCH];      // 29.1 KB
    __shared__ int s_ws[PW], s_we[PW], s_hs[PH], s_he[PH];
    __shared__ int s_b;

    const int H = 64, W = 64;
    const int r = blockIdx.x;
    const float* roi = rois + (size_t)r * 5;

    if (threadIdx.x == 0) {
        const int xs = (int)rintf(__fmul_rn(roi[1], SCALE));
        const int ys = (int)rintf(__fmul_rn(roi[2], SCALE));
        const int xe = (int)rintf(__fmul_rn(roi[3], SCALE));
        const int ye = (int)rintf(__fmul_rn(roi[4], SCALE));
        const float roi_w = (float)max(xe - xs + 1, 1);
        const float roi_h = (float)max(ye - ys + 1, 1);
        const float rc7 = __uint_as_float(0x3E124925u);   // RN(1/7): XLA rewrite
        const float bw = __fmul_rn(roi_w, rc7);
        const float bh = __fmul_rn(roi_h, rc7);
        #pragma unroll
        for (int p = 0; p < 7; ++p) {
            const float pf = (float)p;
            s_ws[p] = min(max((int)floorf(__fmul_rn(pf, bw)) + xs, 0), W);
            s_we[p] = min(max((int)ceilf(__fmul_rn(pf + 1.0f, bw)) + xs, 0), W);
            s_hs[p] = min(max((int)floorf(__fmul_rn(pf, bh)) + ys, 0), H);
            s_he[p] = min(max((int)ceilf(__fmul_rn(pf + 1.0f, bh)) + ys, 0), H);
        }
        s_b = (int)roi[0];
    }
    __syncthreads();

    const int wid  = threadIdx.x >> 5;
    const int lane = threadIdx.x & 31;
    const float* xb = g_xt + (size_t)s_b * 4096 * 256;
    float* out_r = out + (size_t)r * 12544;

    // Two bin groups through the same sbin buffer.
    #pragma unroll 1
    for (int g = 0; g < 2; ++g) {
        const int gs = (g == 0) ? 0 : 28;
        const int ge = (g == 0) ? 28 : 49;
        const int n  = ge - gs;                  // 28 or 21

        // Phase 1: pool bins [gs, ge), one per warp.
        for (int bin = gs + wid; bin < ge; bin += 8) {
            const int ph = bin / 7, pw = bin % 7;
            const int hs = s_hs[ph], he = s_he[ph];
            const int ws = s_ws[pw], we = s_we[pw];

            float4 m0 = make_float4(-FLT_MAX, -FLT_MAX, -FLT_MAX, -FLT_MAX);
            float4 m1 = m0;

            for (int h = hs; h < he; ++h) {
                const float* p = xb + ((size_t)(h * 64 + ws)) * 256 + 4 * lane;
                for (int w = ws; w < we; ++w, p += 256) {
                    const float4 a = *(const float4*)p;
                    const float4 c = *(const float4*)(p + 128);
                    m0 = fmax4(m0, a);
                    m1 = fmax4(m1, c);
                }
            }
            if ((he <= hs) || (we <= ws)) {
                m0 = make_float4(0.0f, 0.0f, 0.0f, 0.0f);
                m1 = m0;
            }
            float* s = sbin + (bin - gs) * SPITCH + 4 * lane;
            *(float4*)s = m0;
            *(float4*)(s + 128) = m1;
        }
        __syncthreads();

        // Phase 2: flush group to gmem. j enumerates (c, bb) pairs with
        // bb fastest; out index i = c*49 + gs + bb (>= 21-contiguous runs).
        {
            int j = threadIdx.x;
            int c = j / n;
            int bb = j - c * n;
            const int dc = NTHR / n;             // 9 (n=28) or 12 (n=21)
            const int db = NTHR - dc * n;        // 4  (n=28) or 4  (n=21)
            const int total = 256 * n;
            #pragma unroll 1
            for (; j < total; j += NTHR) {
                out_r[c * 49 + gs + bb] = sbin[bb * SPITCH + c];
                c += dc; bb += db;
                if (bb >= n) { bb -= n; ++c; }
            }
        }
        __syncthreads();
    }
}

extern "C" void kernel_launch(void* const* d_in, const int* in_sizes, int n_in,
                              void* d_out, int out_size)
{
    const float* x    = (const float*)d_in[0];
    const float* rois = (const float*)d_in[1];
    float* out        = (float*)d_out;
    const int R = in_sizes[1] / 5;

    dim3 tg(128, 8, 2);
    transpose_kernel<<<tg, 256>>>(x);
    roipool_cl_kernel<<<R, NTHR>>>(rois, out);
}

// round 9
// speedup vs baseline: 1.2573x; 1.2573x over previous
#include <cuda_runtime.h>
#include <cfloat>

// Caffe-style RoI max pooling, bit-exact to the XLA-executed JAX reference.
//   x: [2,256,64,64] f32, rois: [2048,5] f32 -> out: [2048,256,7,7] f32
// Numerics: bin = roi_dim * RN(1/7) (0x3E124925) — XLA rewrites const-division
// into reciprocal multiply; rintf == jnp.round; __fmul_rn for boundary muls.
//
// K1: transpose x -> xt[b][h][w][c] (channels-last) device scratch.
// K2: one block per roi, one bin per warp, warp-uniform bounds. Inner w-loop
//     unrolled x2 with independent accumulator pairs -> 4 LDG.128 in flight
//     (the kernel is per-warp-MLP bound, proven by round 8's occupancy
//     experiment). sbin pitch 258 -> phase-2 LDS conflicts 4-way -> 2-way.

#define PH 7
#define PW 7
#define SCALE 0.0625f
#define NTHR 256
#define SPITCH 258                 // floats per bin row; stride mod 32 == 2

__device__ float g_xt[2 * 64 * 64 * 256];   // [b][h][w][c]

// ---- K1: [b][c][hw] -> [b][hw][c] tiled transpose ----
__global__ void __launch_bounds__(256)
transpose_kernel(const float* __restrict__ x)
{
    __shared__ float t[32][33];
    const int tx = threadIdx.x & 31;
    const int ty = threadIdx.x >> 5;
    const int hw0 = blockIdx.x * 32;
    const int c0  = blockIdx.y * 32;
    const int b   = blockIdx.z;
    const float* src = x + (size_t)b * 256 * 4096;
    float* dst = g_xt + (size_t)b * 4096 * 256;

    #pragma unroll
    for (int i = 0; i < 32; i += 8)
        t[ty + i][tx] = src[(size_t)(c0 + ty + i) * 4096 + hw0 + tx];
    __syncthreads();
    #pragma unroll
    for (int i = 0; i < 32; i += 8)
        dst[(size_t)(hw0 + ty + i) * 256 + c0 + tx] = t[tx][ty + i];
}

__device__ __forceinline__ float4 fmax4(float4 a, float4 b) {
    return make_float4(fmaxf(a.x, b.x), fmaxf(a.y, b.y),
                       fmaxf(a.z, b.z), fmaxf(a.w, b.w));
}

// ---- K2: pooling, one block per roi ----
__global__ void __launch_bounds__(NTHR, 4)
roipool_cl_kernel(const float* __restrict__ rois,
                  float* __restrict__ out)
{
    __shared__ float sbin[49 * SPITCH];     // 50.6 KB: [bin][channel]
    __shared__ int s_ws[PW], s_we[PW], s_hs[PH], s_he[PH];
    __shared__ int s_b;

    const int H = 64, W = 64;
    const int r = blockIdx.x;
    const float* roi = rois + (size_t)r * 5;

    if (threadIdx.x == 0) {
        const int xs = (int)rintf(__fmul_rn(roi[1], SCALE));
        const int ys = (int)rintf(__fmul_rn(roi[2], SCALE));
        const int xe = (int)rintf(__fmul_rn(roi[3], SCALE));
        const int ye = (int)rintf(__fmul_rn(roi[4], SCALE));
        const float roi_w = (float)max(xe - xs + 1, 1);
        const float roi_h = (float)max(ye - ys + 1, 1);
        const float rc7 = __uint_as_float(0x3E124925u);   // RN(1/7): XLA rewrite
        const float bw = __fmul_rn(roi_w, rc7);
        const float bh = __fmul_rn(roi_h, rc7);
        #pragma unroll
        for (int p = 0; p < 7; ++p) {
            const float pf = (float)p;
            s_ws[p] = min(max((int)floorf(__fmul_rn(pf, bw)) + xs, 0), W);
            s_we[p] = min(max((int)ceilf(__fmul_rn(pf + 1.0f, bw)) + xs, 0), W);
            s_hs[p] = min(max((int)floorf(__fmul_rn(pf, bh)) + ys, 0), H);
            s_he[p] = min(max((int)ceilf(__fmul_rn(pf + 1.0f, bh)) + ys, 0), H);
        }
        s_b = (int)roi[0];
    }
    __syncthreads();

    const int wid  = threadIdx.x >> 5;      // 8 warps
    const int lane = threadIdx.x & 31;
    const float* xb = g_xt + (size_t)s_b * 4096 * 256;

    // Phase 1: one bin per warp; lanes cover channels [4L,4L+4) and
    // [128+4L,128+4L+4). w-loop unrolled x2, split accumulators -> 4 in-flight
    // LDG.128 per iteration.
    for (int bin = wid; bin < 49; bin += 8) {
        const int ph = bin / 7, pw = bin % 7;
        const int hs = s_hs[ph], he = s_he[ph];
        const int ws = s_ws[pw], we = s_we[pw];

        const float4 NEG = make_float4(-FLT_MAX, -FLT_MAX, -FLT_MAX, -FLT_MAX);
        float4 m0a = NEG, m1a = NEG, m0b = NEG, m1b = NEG;

        for (int h = hs; h < he; ++h) {
            const float* p = xb + ((size_t)(h * 64 + ws)) * 256 + 4 * lane;
            int w = ws;
            for (; w + 2 <= we; w += 2, p += 512) {
                const float4 a0 = *(const float4*)p;
                const float4 c0 = *(const float4*)(p + 128);
                const float4 a1 = *(const float4*)(p + 256);
                const float4 c1 = *(const float4*)(p + 384);
                m0a = fmax4(m0a, a0);
                m1a = fmax4(m1a, c0);
                m0b = fmax4(m0b, a1);
                m1b = fmax4(m1b, c1);
            }
            if (w < we) {
                const float4 a0 = *(const float4*)p;
                const float4 c0 = *(const float4*)(p + 128);
                m0a = fmax4(m0a, a0);
                m1a = fmax4(m1a, c0);
            }
        }
        float4 m0 = fmax4(m0a, m0b);
        float4 m1 = fmax4(m1a, m1b);
        if ((he <= hs) || (we <= ws)) {
            m0 = make_float4(0.0f, 0.0f, 0.0f, 0.0f);
            m1 = m0;
        }

        // STS.64 pairs (rows are 8B-aligned with SPITCH=258), conflict-free.
        float* s = sbin + bin * SPITCH + 4 * lane;
        *(float2*)(s)       = make_float2(m0.x, m0.y);
        *(float2*)(s + 2)   = make_float2(m0.z, m0.w);
        *(float2*)(s + 128) = make_float2(m1.x, m1.y);
        *(float2*)(s + 130) = make_float2(m1.z, m1.w);
    }
    __syncthreads();

    // Phase 2: coalesced linear store of the roi's 12544 outputs.
    // i = c*49 + bin; maintain (c, bin) incrementally (256 = 5*49 + 11).
    float* out_r = out + (size_t)r * 12544;
    {
        int i = threadIdx.x;
        int c = i / 49;
        int bin = i - c * 49;
        #pragma unroll 1
        for (int k = 0; k < 49; ++k) {
            out_r[i] = sbin[bin * SPITCH + c];
            i += NTHR;
            c += 5; bin += 11;
            if (bin >= 49) { bin -= 49; ++c; }
        }
    }
}

extern "C" void kernel_launch(void* const* d_in, const int* in_sizes, int n_in,
                              void* d_out, int out_size)
{
    const float* x    = (const float*)d_in[0];
    const float* rois = (const float*)d_in[1];
    float* out        = (float*)d_out;
    const int R = in_sizes[1] / 5;

    dim3 tg(128, 8, 2);
    transpose_kernel<<<tg, 256>>>(x);
    roipool_cl_kernel<<<R, NTHR>>>(rois, out);
}

// round 10
// speedup vs baseline: 1.6550x; 1.3164x over previous
#include <cuda_runtime.h>
#include <cfloat>

// Caffe-style RoI max pooling, bit-exact to the XLA-executed JAX reference.
//   x: [2,256,64,64] f32, rois: [2048,5] f32 -> out: [2048,256,7,7] f32
// Numerics: bin = roi_dim * RN(1/7) (0x3E124925) — XLA rewrites const-division
// into reciprocal multiply; rintf == jnp.round; __fmul_rn for boundary muls.
//
// Pipeline:
//   K1: transpose x -> xt[b][h][w][c] (channels-last).
//   K2: build 2x2/2x1/1x2 max tables R2/C2/P2 (channels-last, 8MB each).
//   K3: pooling. Window max = max of overlapping 2x2 chunks (max is
//       idempotent, so the last chunk is clamped to end-2 and may overlap
//       the previous one). Lookups per bin: ceil(nh/2)*ceil(nw/2) instead
//       of nh*nw -> ~2.5x fewer global-read wavefronts.

#define PH 7
#define PW 7
#define SCALE 0.0625f
#define NTHR 256
#define SPITCH 258                 // floats per bin row; stride mod 32 == 2

__device__ float g_xt[2 * 64 * 64 * 256];   // [b][h][w][c]
__device__ float g_r2[2 * 64 * 64 * 256];   // 2x2 block max
__device__ float g_p2[2 * 64 * 64 * 256];   // horizontal pair max (w, w+1)
__device__ float g_c2[2 * 64 * 64 * 256];   // vertical pair max (h, h+1)

// ---- K1: [b][c][hw] -> [b][hw][c] tiled transpose ----
__global__ void __launch_bounds__(256)
transpose_kernel(const float* __restrict__ x)
{
    __shared__ float t[32][33];
    const int tx = threadIdx.x & 31;
    const int ty = threadIdx.x >> 5;
    const int hw0 = blockIdx.x * 32;
    const int c0  = blockIdx.y * 32;
    const int b   = blockIdx.z;
    const float* src = x + (size_t)b * 256 * 4096;
    float* dst = g_xt + (size_t)b * 4096 * 256;

    #pragma unroll
    for (int i = 0; i < 32; i += 8)
        t[ty + i][tx] = src[(size_t)(c0 + ty + i) * 4096 + hw0 + tx];
    __syncthreads();
    #pragma unroll
    for (int i = 0; i < 32; i += 8)
        dst[(size_t)(hw0 + ty + i) * 256 + c0 + tx] = t[tx][ty + i];
}

__device__ __forceinline__ float4 fmax4(float4 a, float4 b) {
    return make_float4(fmaxf(a.x, b.x), fmaxf(a.y, b.y),
                       fmaxf(a.z, b.z), fmaxf(a.w, b.w));
}

// ---- K2: build pair/block max tables from xt ----
__global__ void __launch_bounds__(256)
build_tables_kernel()
{
    const int h = blockIdx.x;           // 0..63
    const int b = blockIdx.y;           // 0..1
    const int h1 = min(h + 1, 63);
    const float* base = g_xt + (size_t)b * 4096 * 256;
    float* p2 = g_p2 + (size_t)b * 4096 * 256;
    float* c2 = g_c2 + (size_t)b * 4096 * 256;
    float* r2 = g_r2 + (size_t)b * 4096 * 256;

    // 64 w positions * 64 float4-groups of channels = 4096 tasks per (b,h)
    for (int k = threadIdx.x; k < 64 * 64; k += 256) {
        const int w  = k >> 6;
        const int c4 = (k & 63) * 4;
        const int w1 = min(w + 1, 63);
        const float4 a  = *(const float4*)(base + ((size_t)(h  * 64 + w )) * 256 + c4);
        const float4 bb = *(const float4*)(base + ((size_t)(h  * 64 + w1)) * 256 + c4);
        const float4 cc = *(const float4*)(base + ((size_t)(h1 * 64 + w )) * 256 + c4);
        const float4 dd = *(const float4*)(base + ((size_t)(h1 * 64 + w1)) * 256 + c4);
        const float4 ph2 = fmax4(a, bb);
        const float4 pv2 = fmax4(a, cc);
        const size_t o = ((size_t)(h * 64 + w)) * 256 + c4;
        *(float4*)(p2 + o) = ph2;
        *(float4*)(c2 + o) = pv2;
        *(float4*)(r2 + o) = fmax4(ph2, fmax4(cc, dd));
    }
}

// ---- K3: pooling, one block per roi ----
__global__ void __launch_bounds__(NTHR, 4)
roipool_cl_kernel(const float* __restrict__ rois,
                  float* __restrict__ out)
{
    __shared__ float sbin[49 * SPITCH];     // 50.6 KB: [bin][channel]
    __shared__ int s_ws[PW], s_we[PW], s_hs[PH], s_he[PH];
    __shared__ int s_b;

    const int H = 64, W = 64;
    const int r = blockIdx.x;
    const float* roi = rois + (size_t)r * 5;

    if (threadIdx.x == 0) {
        const int xs = (int)rintf(__fmul_rn(roi[1], SCALE));
        const int ys = (int)rintf(__fmul_rn(roi[2], SCALE));
        const int xe = (int)rintf(__fmul_rn(roi[3], SCALE));
        const int ye = (int)rintf(__fmul_rn(roi[4], SCALE));
        const float roi_w = (float)max(xe - xs + 1, 1);
        const float roi_h = (float)max(ye - ys + 1, 1);
        const float rc7 = __uint_as_float(0x3E124925u);   // RN(1/7): XLA rewrite
        const float bw = __fmul_rn(roi_w, rc7);
        const float bh = __fmul_rn(roi_h, rc7);
        #pragma unroll
        for (int p = 0; p < 7; ++p) {
            const float pf = (float)p;
            s_ws[p] = min(max((int)floorf(__fmul_rn(pf, bw)) + xs, 0), W);
            s_we[p] = min(max((int)ceilf(__fmul_rn(pf + 1.0f, bw)) + xs, 0), W);
            s_hs[p] = min(max((int)floorf(__fmul_rn(pf, bh)) + ys, 0), H);
            s_he[p] = min(max((int)ceilf(__fmul_rn(pf + 1.0f, bh)) + ys, 0), H);
        }
        s_b = (int)roi[0];
    }
    __syncthreads();

    const int wid  = threadIdx.x >> 5;      // 8 warps
    const int lane = threadIdx.x & 31;
    const size_t bplane = (size_t)s_b * 4096 * 256;

    // Phase 1: one bin per warp. Window max via overlapping 2x2 (R2),
    // 1x2 (P2), 2x1 (C2) or 1x1 (xt) chunks; last chunk clamped inward.
    for (int bin = wid; bin < 49; bin += 8) {
        const int ph = bin / 7, pw = bin % 7;
        const int hs = s_hs[ph], he = s_he[ph];
        const int ws = s_ws[pw], we = s_we[pw];
        const int nh = he - hs, nw = we - ws;

        const int sh = (nh >= 2) ? 2 : 1;
        const int sw = (nw >= 2) ? 2 : 1;
        const float* tbl =
            (sh == 2) ? ((sw == 2) ? g_r2 : g_c2)
                      : ((sw == 2) ? g_p2 : g_xt);
        tbl += bplane;

        const int hlast = he - sh;
        const int wlast = we - sw;

        float4 m0 = make_float4(-FLT_MAX, -FLT_MAX, -FLT_MAX, -FLT_MAX);
        float4 m1 = m0;

        for (int h = hs; h < he; h += sh) {
            const int hh = min(h, hlast);
            const float* rowp = tbl + ((size_t)(hh * 64)) * 256 + 4 * lane;
            for (int w = ws; w < we; w += sw) {
                const int ww = min(w, wlast);
                const float* p = rowp + ww * 256;
                m0 = fmax4(m0, *(const float4*)p);
                m1 = fmax4(m1, *(const float4*)(p + 128));
            }
        }
        if (nh <= 0 || nw <= 0) {
            m0 = make_float4(0.0f, 0.0f, 0.0f, 0.0f);
            m1 = m0;
        }

        float* s = sbin + bin * SPITCH + 4 * lane;
        *(float2*)(s)       = make_float2(m0.x, m0.y);
        *(float2*)(s + 2)   = make_float2(m0.z, m0.w);
        *(float2*)(s + 128) = make_float2(m1.x, m1.y);
        *(float2*)(s + 130) = make_float2(m1.z, m1.w);
    }
    __syncthreads();

    // Phase 2: coalesced linear store; (c,bin) maintained incrementally.
    float* out_r = out + (size_t)r * 12544;
    {
        int i = threadIdx.x;
        int c = i / 49;
        int bin = i - c * 49;
        #pragma unroll 1
        for (int k = 0; k < 49; ++k) {
            out_r[i] = sbin[bin * SPITCH + c];
            i += NTHR;
            c += 5; bin += 11;
            if (bin >= 49) { bin -= 49; ++c; }
        }
    }
}

extern "C" void kernel_launch(void* const* d_in, const int* in_sizes, int n_in,
                              void* d_out, int out_size)
{
    const float* x    = (const float*)d_in[0];
    const float* rois = (const float*)d_in[1];
    float* out        = (float*)d_out;
    const int R = in_sizes[1] / 5;

    dim3 tg(128, 8, 2);
    transpose_kernel<<<tg, 256>>>(x);
    dim3 bg(64, 2);
    build_tables_kernel<<<bg, 256>>>();
    roipool_cl_kernel<<<R, NTHR>>>(rois, out);
}